// round 16
// baseline (speedup 1.0000x reference)
#include <cuda_runtime.h>
#include <cstdint>

// Problem constants
#define BB     8
#define RR     2048
#define CC     4096
#define NROWS  (BB * RR)
#define WORDS  (CC / 32)
#define K_FRONT 1228u               // int(4096*0.30)
#define K_RAND  409u                // int(4096*0.10)

#define T1  512
#define EPT 8

// Front bracket: scores ~ N(0,1); q30 of 4096 in (-0.70, -0.35) w/ 8.5-sigma margin.
#define KLO  0x40CCCCCCu
#define FRNG 0x00800000u            // KHI - KLO = 2^23 exactly
#define BELOW_THR 0xBF333334u       // d >= this  <=>  skey < KLO (unsigned wrap)
#define PIV  (1u << 29)             // rand pivot: E[count]=512 >= 409

// ---- scratch ----
__device__ uint32_t g_smask[NROWS * WORDS];   // student keep-bits, 8 MB
__device__ uint32_t g_front0[BB * WORDS];     // front bits for row 0 of each batch

// ---- threefry2x32 rounds, heavy ops steered to the fma pipe ----
__device__ __forceinline__ void tf_round(uint32_t& x0, uint32_t& x1,
                                         uint32_t rm, uint32_t m1) {
    x0 = x0 * m1 + x1;
    unsigned long long p = (unsigned long long)x1 * rm;
    x1 = ((uint32_t)p ^ (uint32_t)(p >> 32)) ^ x0;
}
__device__ __forceinline__ void tf_round_ks(uint32_t& x0, uint32_t& x1,
                                            uint32_t rm, uint32_t ks) {
    x0 = x0 + ks + x1;
    unsigned long long p = (unsigned long long)x1 * rm;
    x1 = ((uint32_t)p ^ (uint32_t)(p >> 32)) ^ x0;
}

// Left-aligned ordering key of jax.random.uniform at flat index g (low 9 bits 0).
// key=(0,42): ks=[0,42,0x1BD11BF0]. 20 rounds, 5 injections, x0-adds folded.
__device__ __forceinline__ uint32_t rand_key(uint32_t g,
        uint32_t m13, uint32_t m15, uint32_t m26, uint32_t m6,
        uint32_t m17, uint32_t m29, uint32_t m16, uint32_t m24, uint32_t m1) {
    uint32_t x0 = 0u, x1 = g + 42u;
    tf_round(x0,x1,m13,m1); tf_round(x0,x1,m15,m1); tf_round(x0,x1,m26,m1); tf_round(x0,x1,m6,m1);
    x1 += 0x1BD11BF1u;
    tf_round_ks(x0,x1,m17,42u);
    tf_round(x0,x1,m29,m1); tf_round(x0,x1,m16,m1); tf_round(x0,x1,m24,m1);
    x1 += 2u;
    tf_round_ks(x0,x1,m13,0x1BD11BF0u);
    tf_round(x0,x1,m15,m1); tf_round(x0,x1,m26,m1); tf_round(x0,x1,m6,m1);
    x1 += 45u;
    tf_round(x0,x1,m17,m1); tf_round(x0,x1,m29,m1);
    tf_round(x0,x1,m16,m1); tf_round(x0,x1,m24,m1);
    x1 += 0x1BD11BF4u;
    tf_round_ks(x0,x1,m13,42u);
    tf_round(x0,x1,m15,m1); tf_round(x0,x1,m26,m1); tf_round(x0,x1,m6,m1);
    x0 += 0x1BD11BF0u;  x1 += 5u;
    return (x0 ^ x1) & 0xFFFFFE00u;
}

__device__ __forceinline__ uint32_t warp_inscan(uint32_t v, int lane) {
#pragma unroll
    for (int d = 1; d < 32; d <<= 1) {
        uint32_t y = __shfl_up_sync(0xFFFFFFFFu, v, d);
        if (lane >= d) v += y;
    }
    return v;
}
__device__ __forceinline__ uint32_t warp_exscan(uint32_t v, int lane) {
    return warp_inscan(v, lane) - v;
}

// Exact full-range fallback: top-down 8-bit radix select (block-wide).
__device__ __noinline__ void radix8_fallback(const uint32_t (&key)[EPT], uint32_t K,
                                             int npass, int t, int lane,
                                             uint32_t* hist, uint32_t* s_ctl,
                                             uint32_t& T, uint32_t& need) {
    uint32_t prefix = 0, kk = K - 1;
    for (int p = 0; p < npass; p++) {
        const int shift = 24 - 8 * p;
        if (t < 256) hist[t] = 0;
        __syncthreads();
        for (int j = 0; j < EPT; j++) {
            uint32_t kv = key[j];
            bool m = (p == 0) || ((kv >> (shift + 8)) == prefix);
            if (m) atomicAdd(&hist[(kv >> shift) & 255u], 1u);
        }
        __syncthreads();
        if (t < 32) {
            uint32_t h[8], sum = 0;
            for (int b = 0; b < 8; b++) { h[b] = hist[8 * t + b]; sum += h[b]; }
            uint32_t run = warp_exscan(sum, lane);
            for (int b = 0; b < 8; b++) {
                if (kk >= run && kk < run + h[b]) {
                    s_ctl[0] = (uint32_t)(8 * t + b);
                    s_ctl[1] = kk - run;
                }
                run += h[b];
            }
        }
        __syncthreads();
        prefix = (prefix << 8) | s_ctl[0];
        kk = s_ctl[1];
        __syncthreads();
    }
    T = prefix << (32 - 8 * npass);
    need = kk + 1;
}

// ============================================================================
// Kernel 1 (chunked by qoff): bracketed dual select, singleton-bin shortcut,
// guarded locate loops. launch_bounds(576,2) caps regs at 56 so ONE k2 block
// can co-reside with two k1 blocks (2*512*56 + 256*32 = 65536 regs exactly).
// ============================================================================
__global__ __launch_bounds__(576, 2) void k1_select(const float* __restrict__ score,
        int qoff,
        uint32_t m13, uint32_t m15, uint32_t m26, uint32_t m6,
        uint32_t m17, uint32_t m29, uint32_t m16, uint32_t m24, uint32_t m1) {
    const int q = qoff + blockIdx.x;
    const int t = threadIdx.x;
    const int wi = t >> 5, lane = t & 31;
    const uint32_t lmask_lt = (1u << lane) - 1u;
    const float* row = score + (size_t)q * CC;

    __shared__ __align__(16) uint32_t hist[10496];
    __shared__ uint32_t s_warpA[16], s_warpB[16];
    __shared__ uint32_t s_ctl[6];
    __shared__ uint32_t s_cnt[2];
    __shared__ uint32_t s_val[2];
    uint32_t* s_bf = hist;
    uint32_t* s_br = hist + 128;
    uint32_t* s_pf = hist + 256;
    uint32_t* s_pr = hist + 384;

    {
        uint4* h4 = (uint4*)hist;
        uint4 z = make_uint4(0, 0, 0, 0);
#pragma unroll
        for (int i = 0; i < 6; i++) {
            int idx = t + i * T1;
            if (idx < 2624) h4[idx] = z;
        }
    }
    if (t < 6) s_ctl[t] = 0;
    __syncthreads();

    uint32_t skey[EPT], rkey[EPT];
    uint32_t cl = 0;
#pragma unroll
    for (int j = 0; j < EPT; j++) {
        int c = j * T1 + t;
        uint32_t u = __float_as_uint(row[c]);
        skey[j] = u ^ ((u & 0x80000000u) ? 0xFFFFFFFFu : 0x80000000u);
        rkey[j] = rand_key((uint32_t)(q * CC + c), m13,m15,m26,m6,m17,m29,m16,m24,m1);
        uint32_t d = skey[j] - KLO;
        if (d < FRNG) atomicAdd(&hist[d >> 11], 1u);
        if (rkey[j] < PIV) atomicAdd(&hist[4096u + (rkey[j] >> 17)], 1u);
        cl += (d >= BELOW_THR) ? 1u : 0u;
    }
    cl = __reduce_add_sync(0xFFFFFFFFu, cl);
    if (lane == 0) s_warpB[wi] = cl;
    __syncthreads();

    uint32_t hf[8], hr[8], fs = 0, rs = 0;
    {
        uint4 a0 = *(uint4*)&hist[8 * t];
        uint4 a1 = *(uint4*)&hist[8 * t + 4];
        hf[0]=a0.x; hf[1]=a0.y; hf[2]=a0.z; hf[3]=a0.w;
        hf[4]=a1.x; hf[5]=a1.y; hf[6]=a1.z; hf[7]=a1.w;
        uint4 b0 = *(uint4*)&hist[4096 + 8 * t];
        uint4 b1 = *(uint4*)&hist[4096 + 8 * t + 4];
        hr[0]=b0.x; hr[1]=b0.y; hr[2]=b0.z; hr[3]=b0.w;
        hr[4]=b1.x; hr[5]=b1.y; hr[6]=b1.z; hr[7]=b1.w;
    }
#pragma unroll
    for (int i = 0; i < 8; i++) { fs += hf[i]; rs += hr[i]; }
    uint32_t v = fs | (rs << 16);
    uint32_t incl = warp_inscan(v, lane);
    if (lane == 31) s_warpA[wi] = incl;
    if (t == 0) {
        uint32_t s = 0;
#pragma unroll
        for (int i = 0; i < 16; i++) s += s_warpB[i];
        s_cnt[0] = s;
    }
    __syncthreads();
    if (wi == 0) {
        uint32_t wv = (lane < 16) ? s_warpA[lane] : 0u;
        uint32_t wincl = warp_inscan(wv, lane);
        if (lane < 16) s_warpA[lane] = wincl - wv;
        if (lane == 15) s_cnt[1] = wincl;
    }
    __syncthreads();
    const uint32_t c_lo = s_cnt[0];
    const uint32_t n_in = s_cnt[1] & 0xFFFFu;
    const uint32_t c0   = s_cnt[1] >> 16;
    const uint32_t kfp  = K_FRONT - 1u - c_lo;
    const uint32_t krp  = K_RAND - 1u;
    {
        uint32_t base = (incl - v) + s_warpA[wi];
        uint32_t run = base & 0xFFFFu;
        if (kfp - run < fs) {
#pragma unroll
            for (int i = 0; i < 8; i++) {
                if (kfp >= run && kfp < run + hf[i]) {
                    s_ctl[0] = (uint32_t)(8 * t + i);
                    s_ctl[1] = kfp - run;
                    s_ctl[4] = hf[i];
                }
                run += hf[i];
            }
        }
        run = base >> 16;
        if (krp - run < rs) {
#pragma unroll
            for (int i = 0; i < 8; i++) {
                if (krp >= run && krp < run + hr[i]) {
                    s_ctl[2] = (uint32_t)(8 * t + i);
                    s_ctl[3] = krp - run;
                    s_ctl[5] = hr[i];
                }
                run += hr[i];
            }
        }
    }
    __syncthreads();

    uint32_t Tf, need_f, Tr, need_r, cnt_f = 0, cnt_r = 0;
    const bool fast = (c_lo <= K_FRONT - 1u) &&
                      (K_FRONT - 1u < c_lo + n_in) &&
                      (c0 >= K_RAND);
    if (!fast) {
        radix8_fallback(skey, K_FRONT, 4, t, lane, hist, s_ctl, Tf, need_f);
        radix8_fallback(rkey, K_RAND, 3, t, lane, hist, s_ctl, Tr, need_r);
    } else {
        const uint32_t Bf = s_ctl[0], kf2 = s_ctl[1], cbf = s_ctl[4];
        const uint32_t Br = s_ctl[2], kr2 = s_ctl[3], cbr = s_ctl[5];
        const bool p2f = (cbf != 1u);
        const bool p2r = (cbr != 1u);

#pragma unroll
        for (int j = 0; j < EPT; j++) {
            uint32_t d = skey[j] - KLO;
            if (d < FRNG && (d >> 11) == Bf) {
                if (p2f) atomicAdd(&hist[8192u + (d & 0x7FFu)], 1u);
                else     s_val[0] = skey[j];
            }
            if (rkey[j] < PIV && (rkey[j] >> 17) == Br) {
                if (p2r) atomicAdd(&hist[10240u + ((rkey[j] >> 9) & 0xFFu)], 1u);
                else     s_val[1] = rkey[j];
            }
        }
        __syncthreads();

        if (p2f || p2r) {
            uint32_t g2[4], f2 = 0;
            {
                uint4 c4 = *(uint4*)&hist[8192 + 4 * t];
                g2[0]=c4.x; g2[1]=c4.y; g2[2]=c4.z; g2[3]=c4.w;
            }
#pragma unroll
            for (int i = 0; i < 4; i++) f2 += g2[i];
            uint32_t r2 = (t < 256) ? hist[10240 + t] : 0u;
            uint32_t v2 = f2 | (r2 << 16);
            uint32_t incl2 = warp_inscan(v2, lane);
            if (lane == 31) s_warpA[wi] = incl2;
            __syncthreads();
            if (wi == 0) {
                uint32_t wv = (lane < 16) ? s_warpA[lane] : 0u;
                uint32_t wincl = warp_inscan(wv, lane);
                if (lane < 16) s_warpA[lane] = wincl - wv;
            }
            __syncthreads();
            uint32_t base2 = (incl2 - v2) + s_warpA[wi];
            if (p2f) {
                uint32_t run = base2 & 0xFFFFu;
                if (kf2 - run < f2) {
#pragma unroll
                    for (int i = 0; i < 4; i++) {
                        if (kf2 >= run && kf2 < run + g2[i]) {
                            s_ctl[0] = (uint32_t)(4 * t + i);
                            s_ctl[1] = kf2 - run;
                            s_ctl[4] = g2[i];
                        }
                        run += g2[i];
                    }
                }
            }
            if (p2r && t < 256) {
                uint32_t run = base2 >> 16;
                if (kr2 >= run && kr2 < run + r2) {
                    s_ctl[2] = (uint32_t)t;
                    s_ctl[3] = kr2 - run;
                    s_ctl[5] = r2;
                }
            }
        }
        __syncthreads();
        if (p2f) { Tf = KLO + (Bf << 11) + s_ctl[0]; need_f = s_ctl[1] + 1u; cnt_f = s_ctl[4]; }
        else     { Tf = s_val[0];                    need_f = 1u;            cnt_f = 1u; }
        if (p2r) { Tr = (Br << 17) + (s_ctl[2] << 9); need_r = s_ctl[3] + 1u; cnt_r = s_ctl[5]; }
        else     { Tr = s_val[1];                     need_r = 1u;            cnt_r = 1u; }
    }

    const bool is_row0 = ((q & (RR - 1)) == 0);
    const bool easy = (cnt_f == need_f) && (cnt_r == need_r);
    if (easy) {
#pragma unroll
        for (int j = 0; j < EPT; j++) {
            const int w = j * 16 + wi;
            bool fsel = skey[j] <= Tf;
            bool sel  = fsel || (rkey[j] <= Tr);
            uint32_t keep_w = __ballot_sync(0xFFFFFFFFu, !sel);
            if (lane == 0) g_smask[q * WORDS + w] = keep_w;
            if (is_row0) {
                uint32_t front_w = __ballot_sync(0xFFFFFFFFu, fsel);
                if (lane == 0) g_front0[(q >> 11) * WORDS + w] = front_w;
            }
        }
    } else {
        __syncthreads();
#pragma unroll
        for (int j = 0; j < EPT; j++) {
            uint32_t bfw = __ballot_sync(0xFFFFFFFFu, skey[j] == Tf);
            uint32_t brw = __ballot_sync(0xFFFFFFFFu, rkey[j] == Tr);
            if (lane == 0) { s_bf[j * 16 + wi] = bfw; s_br[j * 16 + wi] = brw; }
        }
        __syncthreads();
        if (t < 32) {
            uint32_t a[4], b[4], sa = 0, sb = 0;
#pragma unroll
            for (int i = 0; i < 4; i++) { a[i] = __popc(s_bf[4 * t + i]); sa += a[i];
                                          b[i] = __popc(s_br[4 * t + i]); sb += b[i]; }
            uint32_t ea = warp_exscan(sa, t), eb = warp_exscan(sb, t);
#pragma unroll
            for (int i = 0; i < 4; i++) {
                s_pf[4 * t + i] = ea; ea += a[i];
                s_pr[4 * t + i] = eb; eb += b[i];
            }
        }
        __syncthreads();
#pragma unroll
        for (int j = 0; j < EPT; j++) {
            const int w = j * 16 + wi;
            uint32_t bfw = s_bf[w], brw = s_br[w];
            bool fsel = (skey[j] < Tf) ||
                        ((skey[j] == Tf) && (s_pf[w] + __popc(bfw & lmask_lt) < need_f));
            bool rsel = (rkey[j] < Tr) ||
                        ((rkey[j] == Tr) && (s_pr[w] + __popc(brw & lmask_lt) < need_r));
            uint32_t keep_w  = __ballot_sync(0xFFFFFFFFu, !(fsel || rsel));
            uint32_t front_w = __ballot_sync(0xFFFFFFFFu, fsel);
            if (lane == 0) {
                g_smask[q * WORDS + w] = keep_w;
                if (is_row0) g_front0[(q >> 11) * WORDS + w] = front_w;
            }
        }
    }
}

// ============================================================================
// Kernel 2 (chunked by batch b): masked transpose tile, streaming ld/st.
// ============================================================================
#define TJ 128
#define TM 32
__global__ __launch_bounds__(256) void k2_transpose(const float* __restrict__ score,
                                                    float* __restrict__ out_s,
                                                    float* __restrict__ out_t,
                                                    int b) {
    __shared__ float ss[TM * TJ];
    __shared__ float st[TM * TJ];
    const int m0 = blockIdx.y * TM;
    const int j0 = blockIdx.x * TJ;
    const int t  = threadIdx.x;
    const int lane = t & 31, wid = t >> 5;

    const float* base = score + (size_t)b * (RR * CC);
#pragma unroll
    for (int k = 0; k < 4; k++) {
        const int mr = wid + 8 * k;
        const int m  = m0 + mr;
        const int j  = 4 * lane;
        const float4 v = __ldcs((const float4*)(base + (size_t)m * 2048 + j0 + j));
        const int r = m >> 1;
        const int c = ((m & 1) << 11) + j0 + j;
        const uint32_t sh = c & 31;
        const uint32_t mw = g_smask[(b * RR + r) * WORDS + (c >> 5)];
        float4 vs;
        vs.x = ((mw >> (sh + 0)) & 1u) ? v.x : 0.0f;
        vs.y = ((mw >> (sh + 1)) & 1u) ? v.y : 0.0f;
        vs.z = ((mw >> (sh + 2)) & 1u) ? v.z : 0.0f;
        vs.w = ((mw >> (sh + 3)) & 1u) ? v.w : 0.0f;
        float4 vt = v;
        if (r == 0) {
            const uint32_t fw = g_front0[b * WORDS + (c >> 5)];
            vt.x = ((fw >> (sh + 0)) & 1u) ? v.x : 0.0f;
            vt.y = ((fw >> (sh + 1)) & 1u) ? v.y : 0.0f;
            vt.z = ((fw >> (sh + 2)) & 1u) ? v.z : 0.0f;
            vt.w = ((fw >> (sh + 3)) & 1u) ? v.w : 0.0f;
        }
        const int col4 = lane ^ ((mr >> 2) & 7);
        *(float4*)&ss[mr * TJ + 4 * col4] = vs;
        *(float4*)&st[mr * TJ + 4 * col4] = vt;
    }
    __syncthreads();

    float* os = out_s + (size_t)b * (RR * CC);
    float* ot = out_t + (size_t)b * (RR * CC);
    const int qd = t & 7;
#pragma unroll
    for (int jj = 0; jj < 4; jj++) {
        const int jl = (t >> 3) + 32 * jj;
        const int cw = 4 * ((jl >> 2) ^ qd) + (jl & 3);
        float4 rs, rt;
        rs.x = ss[(4 * qd + 0) * TJ + cw];
        rs.y = ss[(4 * qd + 1) * TJ + cw];
        rs.z = ss[(4 * qd + 2) * TJ + cw];
        rs.w = ss[(4 * qd + 3) * TJ + cw];
        rt.x = st[(4 * qd + 0) * TJ + cw];
        rt.y = st[(4 * qd + 1) * TJ + cw];
        rt.z = st[(4 * qd + 2) * TJ + cw];
        rt.w = st[(4 * qd + 3) * TJ + cw];
        const size_t o = (size_t)(j0 + jl) * CC + m0 + 4 * qd;
        __stwt((float4*)(os + o), rs);
        __stwt((float4*)(ot + o), rt);
    }
}

// ============================================================================
// Launch: per-batch software pipeline across two streams. k1 chunk b fills
// masks for batch b and records ev[b]; k2 chunk b (side stream) waits on
// ev[b], so it overlaps with k1 chunks b+1.. . Joined back before return.
// ============================================================================
extern "C" void kernel_launch(void* const* d_in, const int* in_sizes, int n_in,
                              void* d_out, int out_size) {
    const float* score = (const float*)d_in[0];
    float* out = (float*)d_out;
    float* out_teacher = out + (size_t)BB * RR * CC;

    // Host-side resources, created once (no device memory involved).
    static cudaStream_t s1 = nullptr;
    static cudaEvent_t ev[BB], ev_join;
    if (s1 == nullptr) {
        cudaStreamCreateWithFlags(&s1, cudaStreamNonBlocking);
        for (int b = 0; b < BB; b++)
            cudaEventCreateWithFlags(&ev[b], cudaEventDisableTiming);
        cudaEventCreateWithFlags(&ev_join, cudaEventDisableTiming);
    }

    for (int b = 0; b < BB; b++) {
        k1_select<<<RR, T1>>>(score, b * RR,
            1u << 13, 1u << 15, 1u << 26, 1u << 6,
            1u << 17, 1u << 29, 1u << 16, 1u << 24, 1u);
        cudaEventRecord(ev[b], 0);
    }
    dim3 grid(CC / 2 / TJ, CC / TM, 1);   // (16, 128)
    for (int b = 0; b < BB; b++) {
        cudaStreamWaitEvent(s1, ev[b], 0);
        k2_transpose<<<grid, 256, 0, s1>>>(score, out, out_teacher, b);
    }
    cudaEventRecord(ev_join, s1);
    cudaStreamWaitEvent(0, ev_join, 0);   // join side stream back into capture
}

// round 17
// speedup vs baseline: 1.0299x; 1.0299x over previous
#include <cuda_runtime.h>
#include <cstdint>

// Problem constants
#define BB     8
#define RR     2048
#define CC     4096
#define NROWS  (BB * RR)
#define WORDS  (CC / 32)
#define K_FRONT 1228u               // int(4096*0.30)
#define K_RAND  409u                // int(4096*0.10)

#define T1  512
#define EPT 8

// Front bracket: scores ~ N(0,1); q30 of 4096 in (-0.70, -0.35) w/ 8.5-sigma margin.
#define KLO  0x40CCCCCCu
#define FRNG 0x00800000u            // KHI - KLO = 2^23 exactly
#define BELOW_THR 0xBF333334u       // d >= this  <=>  skey < KLO (unsigned wrap)
#define PIV  (1u << 29)             // rand pivot: E[count]=512 >= 409

// ---- scratch ----
__device__ uint32_t g_smask[NROWS * WORDS];   // student keep-bits, 8 MB
__device__ uint32_t g_front0[BB * WORDS];     // front bits for row 0 of each batch

// ---- threefry2x32 rounds, heavy ops steered to the fma pipe ----
__device__ __forceinline__ void tf_round(uint32_t& x0, uint32_t& x1,
                                         uint32_t rm, uint32_t m1) {
    x0 = x0 * m1 + x1;
    unsigned long long p = (unsigned long long)x1 * rm;
    x1 = ((uint32_t)p ^ (uint32_t)(p >> 32)) ^ x0;
}
__device__ __forceinline__ void tf_round_ks(uint32_t& x0, uint32_t& x1,
                                            uint32_t rm, uint32_t ks) {
    x0 = x0 + ks + x1;
    unsigned long long p = (unsigned long long)x1 * rm;
    x1 = ((uint32_t)p ^ (uint32_t)(p >> 32)) ^ x0;
}

// Left-aligned ordering key of jax.random.uniform at flat index g (low 9 bits 0).
// key=(0,42): ks=[0,42,0x1BD11BF0]. 20 rounds, 5 injections, x0-adds folded.
__device__ __forceinline__ uint32_t rand_key(uint32_t g,
        uint32_t m13, uint32_t m15, uint32_t m26, uint32_t m6,
        uint32_t m17, uint32_t m29, uint32_t m16, uint32_t m24, uint32_t m1) {
    uint32_t x0 = 0u, x1 = g + 42u;
    tf_round(x0,x1,m13,m1); tf_round(x0,x1,m15,m1); tf_round(x0,x1,m26,m1); tf_round(x0,x1,m6,m1);
    x1 += 0x1BD11BF1u;
    tf_round_ks(x0,x1,m17,42u);
    tf_round(x0,x1,m29,m1); tf_round(x0,x1,m16,m1); tf_round(x0,x1,m24,m1);
    x1 += 2u;
    tf_round_ks(x0,x1,m13,0x1BD11BF0u);
    tf_round(x0,x1,m15,m1); tf_round(x0,x1,m26,m1); tf_round(x0,x1,m6,m1);
    x1 += 45u;
    tf_round(x0,x1,m17,m1); tf_round(x0,x1,m29,m1);
    tf_round(x0,x1,m16,m1); tf_round(x0,x1,m24,m1);
    x1 += 0x1BD11BF4u;
    tf_round_ks(x0,x1,m13,42u);
    tf_round(x0,x1,m15,m1); tf_round(x0,x1,m26,m1); tf_round(x0,x1,m6,m1);
    x0 += 0x1BD11BF0u;  x1 += 5u;
    return (x0 ^ x1) & 0xFFFFFE00u;
}

__device__ __forceinline__ uint32_t warp_inscan(uint32_t v, int lane) {
#pragma unroll
    for (int d = 1; d < 32; d <<= 1) {
        uint32_t y = __shfl_up_sync(0xFFFFFFFFu, v, d);
        if (lane >= d) v += y;
    }
    return v;
}
__device__ __forceinline__ uint32_t warp_exscan(uint32_t v, int lane) {
    return warp_inscan(v, lane) - v;
}

// Exact full-range fallback: top-down 8-bit radix select (block-wide).
__device__ __noinline__ void radix8_fallback(const uint32_t (&key)[EPT], uint32_t K,
                                             int npass, int t, int lane,
                                             uint32_t* hist, uint32_t* s_ctl,
                                             uint32_t& T, uint32_t& need) {
    uint32_t prefix = 0, kk = K - 1;
    for (int p = 0; p < npass; p++) {
        const int shift = 24 - 8 * p;
        if (t < 256) hist[t] = 0;
        __syncthreads();
        for (int j = 0; j < EPT; j++) {
            uint32_t kv = key[j];
            bool m = (p == 0) || ((kv >> (shift + 8)) == prefix);
            if (m) atomicAdd(&hist[(kv >> shift) & 255u], 1u);
        }
        __syncthreads();
        if (t < 32) {
            uint32_t h[8], sum = 0;
            for (int b = 0; b < 8; b++) { h[b] = hist[8 * t + b]; sum += h[b]; }
            uint32_t run = warp_exscan(sum, lane);
            for (int b = 0; b < 8; b++) {
                if (kk >= run && kk < run + h[b]) {
                    s_ctl[0] = (uint32_t)(8 * t + b);
                    s_ctl[1] = kk - run;
                }
                run += h[b];
            }
        }
        __syncthreads();
        prefix = (prefix << 8) | s_ctl[0];
        kk = s_ctl[1];
        __syncthreads();
    }
    T = prefix << (32 - 8 * npass);
    need = kk + 1;
}

// ============================================================================
// Kernel 1 (chunked by qoff): bracketed dual select, singleton-bin shortcut,
// guarded locate loops. Exact & stable everywhere; full fallback retained.
// 64-reg / 2-block config (measured optimum; 56-reg co-residency regressed).
// ============================================================================
__global__ __launch_bounds__(T1, 2) void k1_select(const float* __restrict__ score,
        int qoff,
        uint32_t m13, uint32_t m15, uint32_t m26, uint32_t m6,
        uint32_t m17, uint32_t m29, uint32_t m16, uint32_t m24, uint32_t m1) {
    const int q = qoff + blockIdx.x;
    const int t = threadIdx.x;
    const int wi = t >> 5, lane = t & 31;
    const uint32_t lmask_lt = (1u << lane) - 1u;
    const float* row = score + (size_t)q * CC;

    __shared__ __align__(16) uint32_t hist[10496];
    __shared__ uint32_t s_warpA[16], s_warpB[16];
    __shared__ uint32_t s_ctl[6];
    __shared__ uint32_t s_cnt[2];
    __shared__ uint32_t s_val[2];
    uint32_t* s_bf = hist;
    uint32_t* s_br = hist + 128;
    uint32_t* s_pf = hist + 256;
    uint32_t* s_pr = hist + 384;

    {
        uint4* h4 = (uint4*)hist;
        uint4 z = make_uint4(0, 0, 0, 0);
#pragma unroll
        for (int i = 0; i < 6; i++) {
            int idx = t + i * T1;
            if (idx < 2624) h4[idx] = z;
        }
    }
    if (t < 6) s_ctl[t] = 0;
    __syncthreads();

    uint32_t skey[EPT], rkey[EPT];
    uint32_t cl = 0;
#pragma unroll
    for (int j = 0; j < EPT; j++) {
        int c = j * T1 + t;
        uint32_t u = __float_as_uint(row[c]);
        skey[j] = u ^ ((u & 0x80000000u) ? 0xFFFFFFFFu : 0x80000000u);
        rkey[j] = rand_key((uint32_t)(q * CC + c), m13,m15,m26,m6,m17,m29,m16,m24,m1);
        uint32_t d = skey[j] - KLO;
        if (d < FRNG) atomicAdd(&hist[d >> 11], 1u);
        if (rkey[j] < PIV) atomicAdd(&hist[4096u + (rkey[j] >> 17)], 1u);
        cl += (d >= BELOW_THR) ? 1u : 0u;
    }
    cl = __reduce_add_sync(0xFFFFFFFFu, cl);
    if (lane == 0) s_warpB[wi] = cl;
    __syncthreads();

    uint32_t hf[8], hr[8], fs = 0, rs = 0;
    {
        uint4 a0 = *(uint4*)&hist[8 * t];
        uint4 a1 = *(uint4*)&hist[8 * t + 4];
        hf[0]=a0.x; hf[1]=a0.y; hf[2]=a0.z; hf[3]=a0.w;
        hf[4]=a1.x; hf[5]=a1.y; hf[6]=a1.z; hf[7]=a1.w;
        uint4 b0 = *(uint4*)&hist[4096 + 8 * t];
        uint4 b1 = *(uint4*)&hist[4096 + 8 * t + 4];
        hr[0]=b0.x; hr[1]=b0.y; hr[2]=b0.z; hr[3]=b0.w;
        hr[4]=b1.x; hr[5]=b1.y; hr[6]=b1.z; hr[7]=b1.w;
    }
#pragma unroll
    for (int i = 0; i < 8; i++) { fs += hf[i]; rs += hr[i]; }
    uint32_t v = fs | (rs << 16);
    uint32_t incl = warp_inscan(v, lane);
    if (lane == 31) s_warpA[wi] = incl;
    if (t == 0) {
        uint32_t s = 0;
#pragma unroll
        for (int i = 0; i < 16; i++) s += s_warpB[i];
        s_cnt[0] = s;
    }
    __syncthreads();
    if (wi == 0) {
        uint32_t wv = (lane < 16) ? s_warpA[lane] : 0u;
        uint32_t wincl = warp_inscan(wv, lane);
        if (lane < 16) s_warpA[lane] = wincl - wv;
        if (lane == 15) s_cnt[1] = wincl;
    }
    __syncthreads();
    const uint32_t c_lo = s_cnt[0];
    const uint32_t n_in = s_cnt[1] & 0xFFFFu;
    const uint32_t c0   = s_cnt[1] >> 16;
    const uint32_t kfp  = K_FRONT - 1u - c_lo;
    const uint32_t krp  = K_RAND - 1u;
    {
        uint32_t base = (incl - v) + s_warpA[wi];
        uint32_t run = base & 0xFFFFu;
        if (kfp - run < fs) {
#pragma unroll
            for (int i = 0; i < 8; i++) {
                if (kfp >= run && kfp < run + hf[i]) {
                    s_ctl[0] = (uint32_t)(8 * t + i);
                    s_ctl[1] = kfp - run;
                    s_ctl[4] = hf[i];
                }
                run += hf[i];
            }
        }
        run = base >> 16;
        if (krp - run < rs) {
#pragma unroll
            for (int i = 0; i < 8; i++) {
                if (krp >= run && krp < run + hr[i]) {
                    s_ctl[2] = (uint32_t)(8 * t + i);
                    s_ctl[3] = krp - run;
                    s_ctl[5] = hr[i];
                }
                run += hr[i];
            }
        }
    }
    __syncthreads();

    uint32_t Tf, need_f, Tr, need_r, cnt_f = 0, cnt_r = 0;
    const bool fast = (c_lo <= K_FRONT - 1u) &&
                      (K_FRONT - 1u < c_lo + n_in) &&
                      (c0 >= K_RAND);
    if (!fast) {
        radix8_fallback(skey, K_FRONT, 4, t, lane, hist, s_ctl, Tf, need_f);
        radix8_fallback(rkey, K_RAND, 3, t, lane, hist, s_ctl, Tr, need_r);
    } else {
        const uint32_t Bf = s_ctl[0], kf2 = s_ctl[1], cbf = s_ctl[4];
        const uint32_t Br = s_ctl[2], kr2 = s_ctl[3], cbr = s_ctl[5];
        const bool p2f = (cbf != 1u);
        const bool p2r = (cbr != 1u);

#pragma unroll
        for (int j = 0; j < EPT; j++) {
            uint32_t d = skey[j] - KLO;
            if (d < FRNG && (d >> 11) == Bf) {
                if (p2f) atomicAdd(&hist[8192u + (d & 0x7FFu)], 1u);
                else     s_val[0] = skey[j];
            }
            if (rkey[j] < PIV && (rkey[j] >> 17) == Br) {
                if (p2r) atomicAdd(&hist[10240u + ((rkey[j] >> 9) & 0xFFu)], 1u);
                else     s_val[1] = rkey[j];
            }
        }
        __syncthreads();

        if (p2f || p2r) {
            uint32_t g2[4], f2 = 0;
            {
                uint4 c4 = *(uint4*)&hist[8192 + 4 * t];
                g2[0]=c4.x; g2[1]=c4.y; g2[2]=c4.z; g2[3]=c4.w;
            }
#pragma unroll
            for (int i = 0; i < 4; i++) f2 += g2[i];
            uint32_t r2 = (t < 256) ? hist[10240 + t] : 0u;
            uint32_t v2 = f2 | (r2 << 16);
            uint32_t incl2 = warp_inscan(v2, lane);
            if (lane == 31) s_warpA[wi] = incl2;
            __syncthreads();
            if (wi == 0) {
                uint32_t wv = (lane < 16) ? s_warpA[lane] : 0u;
                uint32_t wincl = warp_inscan(wv, lane);
                if (lane < 16) s_warpA[lane] = wincl - wv;
            }
            __syncthreads();
            uint32_t base2 = (incl2 - v2) + s_warpA[wi];
            if (p2f) {
                uint32_t run = base2 & 0xFFFFu;
                if (kf2 - run < f2) {
#pragma unroll
                    for (int i = 0; i < 4; i++) {
                        if (kf2 >= run && kf2 < run + g2[i]) {
                            s_ctl[0] = (uint32_t)(4 * t + i);
                            s_ctl[1] = kf2 - run;
                            s_ctl[4] = g2[i];
                        }
                        run += g2[i];
                    }
                }
            }
            if (p2r && t < 256) {
                uint32_t run = base2 >> 16;
                if (kr2 >= run && kr2 < run + r2) {
                    s_ctl[2] = (uint32_t)t;
                    s_ctl[3] = kr2 - run;
                    s_ctl[5] = r2;
                }
            }
        }
        __syncthreads();
        if (p2f) { Tf = KLO + (Bf << 11) + s_ctl[0]; need_f = s_ctl[1] + 1u; cnt_f = s_ctl[4]; }
        else     { Tf = s_val[0];                    need_f = 1u;            cnt_f = 1u; }
        if (p2r) { Tr = (Br << 17) + (s_ctl[2] << 9); need_r = s_ctl[3] + 1u; cnt_r = s_ctl[5]; }
        else     { Tr = s_val[1];                     need_r = 1u;            cnt_r = 1u; }
    }

    const bool is_row0 = ((q & (RR - 1)) == 0);
    const bool easy = (cnt_f == need_f) && (cnt_r == need_r);
    if (easy) {
#pragma unroll
        for (int j = 0; j < EPT; j++) {
            const int w = j * 16 + wi;
            bool fsel = skey[j] <= Tf;
            bool sel  = fsel || (rkey[j] <= Tr);
            uint32_t keep_w = __ballot_sync(0xFFFFFFFFu, !sel);
            if (lane == 0) g_smask[q * WORDS + w] = keep_w;
            if (is_row0) {
                uint32_t front_w = __ballot_sync(0xFFFFFFFFu, fsel);
                if (lane == 0) g_front0[(q >> 11) * WORDS + w] = front_w;
            }
        }
    } else {
        __syncthreads();
#pragma unroll
        for (int j = 0; j < EPT; j++) {
            uint32_t bfw = __ballot_sync(0xFFFFFFFFu, skey[j] == Tf);
            uint32_t brw = __ballot_sync(0xFFFFFFFFu, rkey[j] == Tr);
            if (lane == 0) { s_bf[j * 16 + wi] = bfw; s_br[j * 16 + wi] = brw; }
        }
        __syncthreads();
        if (t < 32) {
            uint32_t a[4], b[4], sa = 0, sb = 0;
#pragma unroll
            for (int i = 0; i < 4; i++) { a[i] = __popc(s_bf[4 * t + i]); sa += a[i];
                                          b[i] = __popc(s_br[4 * t + i]); sb += b[i]; }
            uint32_t ea = warp_exscan(sa, t), eb = warp_exscan(sb, t);
#pragma unroll
            for (int i = 0; i < 4; i++) {
                s_pf[4 * t + i] = ea; ea += a[i];
                s_pr[4 * t + i] = eb; eb += b[i];
            }
        }
        __syncthreads();
#pragma unroll
        for (int j = 0; j < EPT; j++) {
            const int w = j * 16 + wi;
            uint32_t bfw = s_bf[w], brw = s_br[w];
            bool fsel = (skey[j] < Tf) ||
                        ((skey[j] == Tf) && (s_pf[w] + __popc(bfw & lmask_lt) < need_f));
            bool rsel = (rkey[j] < Tr) ||
                        ((rkey[j] == Tr) && (s_pr[w] + __popc(brw & lmask_lt) < need_r));
            uint32_t keep_w  = __ballot_sync(0xFFFFFFFFu, !(fsel || rsel));
            uint32_t front_w = __ballot_sync(0xFFFFFFFFu, fsel);
            if (lane == 0) {
                g_smask[q * WORDS + w] = keep_w;
                if (is_row0) g_front0[(q >> 11) * WORDS + w] = front_w;
            }
        }
    }
}

// ============================================================================
// Kernel 2 (chunked by batch b): masked transpose tile, streaming ld/st.
// ============================================================================
#define TJ 128
#define TM 32
__global__ __launch_bounds__(256) void k2_transpose(const float* __restrict__ score,
                                                    float* __restrict__ out_s,
                                                    float* __restrict__ out_t,
                                                    int b) {
    __shared__ float ss[TM * TJ];
    __shared__ float st[TM * TJ];
    const int m0 = blockIdx.y * TM;
    const int j0 = blockIdx.x * TJ;
    const int t  = threadIdx.x;
    const int lane = t & 31, wid = t >> 5;

    const float* base = score + (size_t)b * (RR * CC);
#pragma unroll
    for (int k = 0; k < 4; k++) {
        const int mr = wid + 8 * k;
        const int m  = m0 + mr;
        const int j  = 4 * lane;
        const float4 v = __ldcs((const float4*)(base + (size_t)m * 2048 + j0 + j));
        const int r = m >> 1;
        const int c = ((m & 1) << 11) + j0 + j;
        const uint32_t sh = c & 31;
        const uint32_t mw = g_smask[(b * RR + r) * WORDS + (c >> 5)];
        float4 vs;
        vs.x = ((mw >> (sh + 0)) & 1u) ? v.x : 0.0f;
        vs.y = ((mw >> (sh + 1)) & 1u) ? v.y : 0.0f;
        vs.z = ((mw >> (sh + 2)) & 1u) ? v.z : 0.0f;
        vs.w = ((mw >> (sh + 3)) & 1u) ? v.w : 0.0f;
        float4 vt = v;
        if (r == 0) {
            const uint32_t fw = g_front0[b * WORDS + (c >> 5)];
            vt.x = ((fw >> (sh + 0)) & 1u) ? v.x : 0.0f;
            vt.y = ((fw >> (sh + 1)) & 1u) ? v.y : 0.0f;
            vt.z = ((fw >> (sh + 2)) & 1u) ? v.z : 0.0f;
            vt.w = ((fw >> (sh + 3)) & 1u) ? v.w : 0.0f;
        }
        const int col4 = lane ^ ((mr >> 2) & 7);
        *(float4*)&ss[mr * TJ + 4 * col4] = vs;
        *(float4*)&st[mr * TJ + 4 * col4] = vt;
    }
    __syncthreads();

    float* os = out_s + (size_t)b * (RR * CC);
    float* ot = out_t + (size_t)b * (RR * CC);
    const int qd = t & 7;
#pragma unroll
    for (int jj = 0; jj < 4; jj++) {
        const int jl = (t >> 3) + 32 * jj;
        const int cw = 4 * ((jl >> 2) ^ qd) + (jl & 3);
        float4 rs, rt;
        rs.x = ss[(4 * qd + 0) * TJ + cw];
        rs.y = ss[(4 * qd + 1) * TJ + cw];
        rs.z = ss[(4 * qd + 2) * TJ + cw];
        rs.w = ss[(4 * qd + 3) * TJ + cw];
        rt.x = st[(4 * qd + 0) * TJ + cw];
        rt.y = st[(4 * qd + 1) * TJ + cw];
        rt.z = st[(4 * qd + 2) * TJ + cw];
        rt.w = st[(4 * qd + 3) * TJ + cw];
        const size_t o = (size_t)(j0 + jl) * CC + m0 + 4 * qd;
        __stwt((float4*)(os + o), rs);
        __stwt((float4*)(ot + o), rt);
    }
}

// ============================================================================
// Launch: per-batch software pipeline across two streams (R15 config).
// k1 chunk b fills masks for batch b and records ev[b]; k2 chunk b (side
// stream) waits on ev[b]; joined back before return.
// ============================================================================
extern "C" void kernel_launch(void* const* d_in, const int* in_sizes, int n_in,
                              void* d_out, int out_size) {
    const float* score = (const float*)d_in[0];
    float* out = (float*)d_out;
    float* out_teacher = out + (size_t)BB * RR * CC;

    // Host-side resources, created once (no device memory involved).
    static cudaStream_t s1 = nullptr;
    static cudaEvent_t ev[BB], ev_join;
    if (s1 == nullptr) {
        cudaStreamCreateWithFlags(&s1, cudaStreamNonBlocking);
        for (int b = 0; b < BB; b++)
            cudaEventCreateWithFlags(&ev[b], cudaEventDisableTiming);
        cudaEventCreateWithFlags(&ev_join, cudaEventDisableTiming);
    }

    for (int b = 0; b < BB; b++) {
        k1_select<<<RR, T1>>>(score, b * RR,
            1u << 13, 1u << 15, 1u << 26, 1u << 6,
            1u << 17, 1u << 29, 1u << 16, 1u << 24, 1u);
        cudaEventRecord(ev[b], 0);
    }
    dim3 grid(CC / 2 / TJ, CC / TM, 1);   // (16, 128)
    for (int b = 0; b < BB; b++) {
        cudaStreamWaitEvent(s1, ev[b], 0);
        k2_transpose<<<grid, 256, 0, s1>>>(score, out, out_teacher, b);
    }
    cudaEventRecord(ev_join, s1);
    cudaStreamWaitEvent(0, ev_join, 0);   // join side stream back into capture
}